// round 12
// baseline (speedup 1.0000x reference)
#include <cuda_runtime.h>

#define NTOT 200      // histogram bins
#define TILEA 256     // A rows per block
#define TILEB 64      // B cols per block (2 waves of 16 blocks/SM)
#define BLKT 128      // pair-kernel threads (2 A rows per thread)
#define NWARP 4
#define NBUCK 256     // x-sort buckets
#define GROUPS 16     // blocks per array in count/scatter kernels
#define BPB (NBUCK / GROUPS)
#define SCATT 512     // scatter-kernel threads
#define SBATCH 8      // batched loads per thread (MLP)
#define MAXPTS 16384

// Sorted & prescaled points: (x,y,z)*real_size*20, w=|p|^2.
__device__ float4 g_pts[MAXPTS];
// Global bucket histogram for the sort: [arr][bucket].
__device__ int g_cnt[2 * NBUCK];
// 3 raw integer histograms: [0]=00-tri, [1]=01-cross, [2]=11-tri.
// finalize_kernel re-zeroes g_cnt and g_hist -> graph replays start clean.
__device__ int g_hist[3 * NTOT];

__device__ __forceinline__ float fsqrt_approx(float x) {
    float r;
    asm("sqrt.approx.f32 %0, %1;" : "=f"(r) : "f"(x));
    return r;
}

// Phase 1 of the sort: each block counts only its 1/GROUPS slice of one
// array (512 shared atomics instead of 8192), then merges into g_cnt.
__global__ __launch_bounds__(256) void count_kernel(
    const float* __restrict__ pos0, const float* __restrict__ pos1,
    int n0, int n1)
{
    __shared__ int cnt[NBUCK];
    const int arr   = blockIdx.x / GROUPS;
    const int slice = blockIdx.x - arr * GROUPS;
    const float* p  = arr ? pos1 : pos0;
    const int n     = arr ? n1 : n0;
    const int tid   = threadIdx.x;

    const int chunk = (n + GROUPS - 1) / GROUPS;
    const int start = slice * chunk;
    const int end   = min(n, start + chunk);

    cnt[tid] = 0;
    __syncthreads();

    for (int b0 = start; b0 < end; b0 += 256 * 4) {
        float xv[4];
        bool  ok[4];
        #pragma unroll
        for (int k = 0; k < 4; k++) {
            int i = b0 + tid + k * 256;
            ok[k] = (i < end);
            xv[k] = ok[k] ? p[3 * i] : 0.0f;
        }
        #pragma unroll
        for (int k = 0; k < 4; k++) {
            if (ok[k]) {
                int b = (int)(xv[k] * (float)NBUCK);
                b = max(0, min(NBUCK - 1, b));
                atomicAdd(&cnt[b], 1);
            }
        }
    }
    __syncthreads();
    if (cnt[tid]) atomicAdd(&g_cnt[arr * NBUCK + tid], cnt[tid]);
}

// Phase 2: each block loads the precomputed histogram, scans it locally
// (warp shuffle), and scatters only the BPB buckets it owns. Batched x
// loads (MLP=SBATCH); y,z fetched only for owned points (~1/GROUPS).
// Within-bucket order is race-dependent -> fine (histogram is
// permutation-invariant).
__global__ __launch_bounds__(SCATT) void scatter_kernel(
    const float* __restrict__ pos0, const float* __restrict__ pos1,
    const float* __restrict__ rs, int n0, int n1)
{
    __shared__ int cnt[NBUCK];
    __shared__ int cur[BPB];

    const int arr = blockIdx.x / GROUPS;
    const int grp = blockIdx.x - arr * GROUPS;
    const float* p = arr ? pos1 : pos0;
    const int n    = arr ? n1 : n0;
    const int base = arr ? n0 : 0;
    const int lo   = grp * BPB;
    const int tid  = threadIdx.x;

    const float r0 = rs[0] * 20.0f, r1 = rs[1] * 20.0f, r2 = rs[2] * 20.0f;

    if (tid < NBUCK) cnt[tid] = g_cnt[arr * NBUCK + tid];
    __syncthreads();

    // Exclusive scan via single-warp shuffle (lane L owns buckets [8L,8L+8)).
    if (tid < 32) {
        int v[8], s = 0;
        #pragma unroll
        for (int j = 0; j < 8; j++) { v[j] = cnt[tid * 8 + j]; s += v[j]; }
        int e = s;
        #pragma unroll
        for (int d = 1; d < 32; d <<= 1) {
            int t = __shfl_up_sync(0xFFFFFFFFu, e, d);
            if (tid >= d) e += t;
        }
        e -= s;
        #pragma unroll
        for (int j = 0; j < 8; j++) { int t = v[j]; cnt[tid * 8 + j] = e; e += t; }
    }
    __syncthreads();
    if (tid < BPB) cur[tid] = cnt[lo + tid];
    __syncthreads();

    for (int b0 = 0; b0 < n; b0 += SCATT * SBATCH) {
        float xv[SBATCH];
        int   bk[SBATCH];
        #pragma unroll
        for (int k = 0; k < SBATCH; k++) {
            int i = b0 + tid + k * SCATT;
            xv[k] = (i < n) ? p[3 * i] : -1.0f;
        }
        #pragma unroll
        for (int k = 0; k < SBATCH; k++) {
            int b = (int)(xv[k] * (float)NBUCK);
            bk[k] = (xv[k] < 0.0f) ? -1 : max(0, min(NBUCK - 1, b));
        }
        #pragma unroll
        for (int k = 0; k < SBATCH; k++) {
            int b = bk[k];
            if (b >= lo && b < lo + BPB) {
                int i = b0 + tid + k * SCATT;
                float y = p[3 * i + 1];
                float z = p[3 * i + 2];
                int pos = atomicAdd(&cur[b - lo], 1);
                float sx = xv[k] * r0, sy = y * r1, sz = z * r2;
                float q = sx * sx; q = fmaf(sy, sy, q); q = fmaf(sz, sz, q);
                g_pts[base + pos] = make_float4(sx, sy, sz, q);
            }
        }
    }
}

// Invert upper-triangle linear index t -> (bi, bj), bj >= bi.
__device__ __forceinline__ void tri_decode(int t, int n, int& bi, int& bj) {
    float fn = (float)(2 * n + 1);
    int b = (int)((fn - sqrtf(fmaxf(fn * fn - 8.0f * (float)t, 0.0f))) * 0.5f);
    if (b < 0) b = 0;
    if (b > n - 1) b = n - 1;
    while (b > 0 && t < b * (2 * n - b + 1) / 2) b--;
    while (b < n - 1 && t >= (b + 1) * (2 * n - b) / 2) b++;
    bi = b;
    bj = b + (t - b * (2 * n - b + 1) / 2);
}

// All three pair regions in one grid; 256x64 work blocks (2 waves/SM);
// x-gap tile cull via sorted endpoints. Inner loop pre-gates on
// s < 40100 (margin-padded) so ~65% of pairs skip MUFU/F2I/ATOMS; actual
// binning is unchanged (d < 200 check on the sqrt result).
__global__ __launch_bounds__(BLKT, 16) void pair_fused_kernel(
    int n0, int n1, int nb0, int nb1, int T0, int C)
{
    __shared__ float4 sB[TILEB];
    __shared__ int    sh[NWARP * NTOT];

    int w    = blockIdx.x >> 2;
    int quar = blockIdx.x & 3;
    int bi, bj, aOff, bOff, nA, nB, histIdx;
    bool diag;
    if (w < T0) {                     // 0-0 triangle
        tri_decode(w, nb0, bi, bj);
        aOff = 0; bOff = 0; nA = n0; nB = n0; histIdx = 0;
        diag = (bi == bj);
    } else if (w < T0 + C) {          // 0-1 cross
        int u = w - T0;
        bi = u / nb1; bj = u - bi * nb1;
        aOff = 0; nA = n0; bOff = n0; nB = n1; histIdx = 1;
        diag = false;
    } else {                          // 1-1 triangle
        int u = w - T0 - C;
        tri_decode(u, nb1, bi, bj);
        aOff = n0; bOff = n0; nA = n1; nB = n1; histIdx = 2;
        diag = (bi == bj);
    }
    const int rowStart  = bi * TILEA;
    const int chunkBase = bj * TILEA + quar * TILEB;
    if (chunkBase >= nB) return;

    // ---- x-gap cull (bucket-granular sort: pad cutoff 200 -> 205) ----
    {
        float a_lo = g_pts[aOff + rowStart].x;
        float a_hi = g_pts[aOff + min(rowStart + TILEA - 1, nA - 1)].x;
        float b_lo = g_pts[bOff + chunkBase].x;
        float b_hi = g_pts[bOff + min(chunkBase + TILEB - 1, nB - 1)].x;
        if (fmaxf(b_lo - a_hi, a_lo - b_hi) > 205.0f) return;
    }

    const int tid = threadIdx.x;
    const int wid = tid >> 5;
    int* myh = &sh[wid * NTOT];

    #pragma unroll
    for (int idx = tid; idx < NWARP * NTOT; idx += BLKT) sh[idx] = 0;

    if (tid < TILEB) {
        int j = chunkBase + tid;
        sB[tid] = (j < nB) ? g_pts[bOff + j]
                           : make_float4(0.f, 0.f, 0.f, 1e30f);
    }

    float ax2[2], ay2[2], az2[2], aw[2];
    int   irow[2];
    #pragma unroll
    for (int t = 0; t < 2; t++) {
        int i = rowStart + tid + t * BLKT;
        irow[t] = i;
        float4 a = (i < nA) ? g_pts[aOff + i]
                            : make_float4(0.f, 0.f, 0.f, 1e30f);
        ax2[t] = -2.0f * a.x; ay2[t] = -2.0f * a.y;
        az2[t] = -2.0f * a.z; aw[t]  = a.w;
    }
    __syncthreads();

    if (diag) {
        #pragma unroll 4
        for (int k = 0; k < TILEB; k++) {
            float4 b = sB[k];
            #pragma unroll
            for (int t = 0; t < 2; t++) {
                float s = aw[t] + b.w;
                s = fmaf(ax2[t], b.x, s);
                s = fmaf(ay2[t], b.y, s);
                s = fmaf(az2[t], b.z, s);
                if (s < 40100.0f) {
                    float d = fsqrt_approx(fmaxf(s, 0.0f));
                    if (d < (float)NTOT && (chunkBase + k) > irow[t])
                        atomicAdd(&myh[(int)d], 1);
                }
            }
        }
    } else {
        #pragma unroll 4
        for (int k = 0; k < TILEB; k++) {
            float4 b = sB[k];
            #pragma unroll
            for (int t = 0; t < 2; t++) {
                float s = aw[t] + b.w;
                s = fmaf(ax2[t], b.x, s);
                s = fmaf(ay2[t], b.y, s);
                s = fmaf(az2[t], b.z, s);
                if (s < 40100.0f) {
                    float d = fsqrt_approx(fmaxf(s, 0.0f));
                    if (d < (float)NTOT)
                        atomicAdd(&myh[(int)d], 1);
                }
            }
        }
    }
    __syncthreads();

    for (int t = tid; t < NTOT; t += BLKT) {
        int v = sh[t] + sh[NTOT + t] + sh[2 * NTOT + t] + sh[3 * NTOT + t];
        if (v) atomicAdd(&g_hist[histIdx * NTOT + t], v);
    }
}

// Single block: normalize all 800 outputs, then zero g_hist/g_cnt for the
// next graph replay.
__global__ void finalize_kernel(const float* __restrict__ count_in,
                                float* __restrict__ out,
                                const float* __restrict__ rs,
                                int n0, int n1)
{
    int idx = threadIdx.x;
    if (idx < 4 * NTOT) {
        int k  = idx % NTOT;
        int ij = idx / NTOT;
        int histIdx = (ij == 0) ? 0 : ((ij == 3) ? 2 : 1);
        float mult  = (ij == 0 || ij == 3) ? 2.0f : 1.0f;
        float na = (float)((ij >> 1) ? n1 : n0);
        float nb = (float)((ij & 1) ? n1 : n0);
        float vol = rs[0] * rs[1] * rs[2];

        float counts = (float)g_hist[histIdx * NTOT + k] * mult;
        double r = 0.025 + (double)k * 0.05;
        float sv = (float)(r * 0.05 * 2.0 * 3.14159265358979323846 * 3.0);
        float density = nb / vol;
        float res = counts / density / sv / na;
        out[idx] = count_in[idx] + res;
    }
    __syncthreads();
    if (idx < 3 * NTOT) g_hist[idx] = 0;
    if (idx < 2 * NBUCK) g_cnt[idx] = 0;
}

extern "C" void kernel_launch(void* const* d_in, const int* in_sizes, int n_in,
                              void* d_out, int out_size)
{
    const float* pos0  = (const float*)d_in[0];
    const float* pos1  = (const float*)d_in[1];
    const float* count = (const float*)d_in[2];
    const float* rs    = (const float*)d_in[3];
    int n0 = in_sizes[0] / 3;
    int n1 = in_sizes[1] / 3;
    float* out = (float*)d_out;

    count_kernel<<<2 * GROUPS, 256>>>(pos0, pos1, n0, n1);
    scatter_kernel<<<2 * GROUPS, SCATT>>>(pos0, pos1, rs, n0, n1);

    int nb0 = (n0 + TILEA - 1) / TILEA;
    int nb1 = (n1 + TILEA - 1) / TILEA;
    int T0 = nb0 * (nb0 + 1) / 2;
    int C  = nb0 * nb1;
    int T1 = nb1 * (nb1 + 1) / 2;
    pair_fused_kernel<<<4 * (T0 + C + T1), BLKT>>>(n0, n1, nb0, nb1, T0, C);

    finalize_kernel<<<1, 4 * NTOT>>>(count, out, rs, n0, n1);
}

// round 14
// speedup vs baseline: 1.0386x; 1.0386x over previous
#include <cuda_runtime.h>

#define NTOT 200      // histogram bins
#define TILEA 256     // A rows per block
#define TILEB 64      // B cols per block (2 waves of 16 blocks/SM)
#define BLKT 128      // pair-kernel threads (2 A rows per thread)
#define NWARP 4
#define NBUCK 256     // x-sort buckets
#define GROUPS 16     // sorter blocks per array
#define BPB (NBUCK / GROUPS)
#define SORTT 512
#define SBATCH 8
#define MAXPTS 16384

// Sorted & prescaled points: (x,y,z)*real_size*20, w=|p|^2.
__device__ float4 g_pts[MAXPTS];
// 3 raw integer histograms: [0]=00-tri, [1]=01-cross, [2]=11-tri.
// finalize_kernel re-zeroes after reading -> graph replays start clean.
__device__ int g_hist[3 * NTOT];

__device__ __forceinline__ float fsqrt_approx(float x) {
    float r;
    asm("sqrt.approx.f32 %0, %1;" : "=f"(r) : "f"(x));
    return r;
}

// Decentralized counting sort (R10-proven): 2*GROUPS blocks, no inter-block
// communication. Every block re-derives the FULL bucket count for its array
// (batched loads, MLP=SBATCH), scans locally, scatters only owned buckets.
__global__ __launch_bounds__(SORTT) void sort_kernel(
    const float* __restrict__ pos0, const float* __restrict__ pos1,
    const float* __restrict__ rs, int n0, int n1)
{
    __shared__ int cnt[NBUCK];
    __shared__ int cur[BPB];

    const int arr = blockIdx.x / GROUPS;
    const int grp = blockIdx.x - arr * GROUPS;
    const float* p = arr ? pos1 : pos0;
    const int n    = arr ? n1 : n0;
    const int base = arr ? n0 : 0;
    const int lo   = grp * BPB;
    const int tid  = threadIdx.x;

    const float r0 = rs[0] * 20.0f, r1 = rs[1] * 20.0f, r2 = rs[2] * 20.0f;

    for (int t = tid; t < NBUCK; t += SORTT) cnt[t] = 0;
    __syncthreads();

    for (int b0 = 0; b0 < n; b0 += SORTT * SBATCH) {
        float xv[SBATCH];
        bool  ok[SBATCH];
        #pragma unroll
        for (int k = 0; k < SBATCH; k++) {
            int i = b0 + tid + k * SORTT;
            ok[k] = (i < n);
            xv[k] = ok[k] ? p[3 * i] : 0.0f;
        }
        #pragma unroll
        for (int k = 0; k < SBATCH; k++) {
            if (ok[k]) {
                int b = (int)(xv[k] * (float)NBUCK);
                b = max(0, min(NBUCK - 1, b));
                atomicAdd(&cnt[b], 1);
            }
        }
    }
    __syncthreads();

    if (tid < 32) {
        int v[8], s = 0;
        #pragma unroll
        for (int j = 0; j < 8; j++) { v[j] = cnt[tid * 8 + j]; s += v[j]; }
        int e = s;
        #pragma unroll
        for (int d = 1; d < 32; d <<= 1) {
            int t = __shfl_up_sync(0xFFFFFFFFu, e, d);
            if (tid >= d) e += t;
        }
        e -= s;
        #pragma unroll
        for (int j = 0; j < 8; j++) { int t = v[j]; cnt[tid * 8 + j] = e; e += t; }
    }
    __syncthreads();
    if (tid < BPB) cur[tid] = cnt[lo + tid];
    __syncthreads();

    for (int b0 = 0; b0 < n; b0 += SORTT * SBATCH) {
        float xv[SBATCH];
        int   bk[SBATCH];
        #pragma unroll
        for (int k = 0; k < SBATCH; k++) {
            int i = b0 + tid + k * SORTT;
            xv[k] = (i < n) ? p[3 * i] : -1.0f;
        }
        #pragma unroll
        for (int k = 0; k < SBATCH; k++) {
            int b = (int)(xv[k] * (float)NBUCK);
            bk[k] = (xv[k] < 0.0f) ? -1 : max(0, min(NBUCK - 1, b));
        }
        #pragma unroll
        for (int k = 0; k < SBATCH; k++) {
            int b = bk[k];
            if (b >= lo && b < lo + BPB) {
                int i = b0 + tid + k * SORTT;
                float y = p[3 * i + 1];
                float z = p[3 * i + 2];
                int pos = atomicAdd(&cur[b - lo], 1);
                float sx = xv[k] * r0, sy = y * r1, sz = z * r2;
                float q = sx * sx; q = fmaf(sy, sy, q); q = fmaf(sz, sz, q);
                g_pts[base + pos] = make_float4(sx, sy, sz, q);
            }
        }
    }
}

// Invert upper-triangle linear index t -> (bi, bj), bj >= bi.
__device__ __forceinline__ void tri_decode(int t, int n, int& bi, int& bj) {
    float fn = (float)(2 * n + 1);
    int b = (int)((fn - sqrtf(fmaxf(fn * fn - 8.0f * (float)t, 0.0f))) * 0.5f);
    if (b < 0) b = 0;
    if (b > n - 1) b = n - 1;
    while (b > 0 && t < b * (2 * n - b + 1) / 2) b--;
    while (b < n - 1 && t >= (b + 1) * (2 * n - b) / 2) b++;
    bi = b;
    bj = b + (t - b * (2 * n - b + 1) / 2);
}

// All three pair regions in one grid; 256x64 blocks (2 waves/SM); x-gap tile
// cull via sorted endpoints. Warp-uniform skip: if no lane of the warp has a
// pair inside the (padded) cutoff, the whole warp branches past the
// MUFU/F2I/ATOMS tail of this iteration. Binning math for surviving pairs is
// bit-identical to the R10 kernel.
__global__ __launch_bounds__(BLKT, 16) void pair_fused_kernel(
    int n0, int n1, int nb0, int nb1, int T0, int C)
{
    __shared__ float4 sB[TILEB];
    __shared__ int    sh[NWARP * NTOT];

    int w    = blockIdx.x >> 2;
    int quar = blockIdx.x & 3;
    int bi, bj, aOff, bOff, nA, nB, histIdx;
    bool diag;
    if (w < T0) {                     // 0-0 triangle
        tri_decode(w, nb0, bi, bj);
        aOff = 0; bOff = 0; nA = n0; nB = n0; histIdx = 0;
        diag = (bi == bj);
    } else if (w < T0 + C) {          // 0-1 cross
        int u = w - T0;
        bi = u / nb1; bj = u - bi * nb1;
        aOff = 0; nA = n0; bOff = n0; nB = n1; histIdx = 1;
        diag = false;
    } else {                          // 1-1 triangle
        int u = w - T0 - C;
        tri_decode(u, nb1, bi, bj);
        aOff = n0; bOff = n0; nA = n1; nB = n1; histIdx = 2;
        diag = (bi == bj);
    }
    const int rowStart  = bi * TILEA;
    const int chunkBase = bj * TILEA + quar * TILEB;
    if (chunkBase >= nB) return;

    // ---- x-gap cull (bucket-granular sort: pad cutoff 200 -> 205) ----
    {
        float a_lo = g_pts[aOff + rowStart].x;
        float a_hi = g_pts[aOff + min(rowStart + TILEA - 1, nA - 1)].x;
        float b_lo = g_pts[bOff + chunkBase].x;
        float b_hi = g_pts[bOff + min(chunkBase + TILEB - 1, nB - 1)].x;
        if (fmaxf(b_lo - a_hi, a_lo - b_hi) > 205.0f) return;
    }

    const int tid = threadIdx.x;
    const int wid = tid >> 5;
    int* myh = &sh[wid * NTOT];

    #pragma unroll
    for (int idx = tid; idx < NWARP * NTOT; idx += BLKT) sh[idx] = 0;

    if (tid < TILEB) {
        int j = chunkBase + tid;
        sB[tid] = (j < nB) ? g_pts[bOff + j]
                           : make_float4(0.f, 0.f, 0.f, 1e30f);
    }

    float ax2[2], ay2[2], az2[2], aw[2];
    int   irow[2];
    #pragma unroll
    for (int t = 0; t < 2; t++) {
        int i = rowStart + tid + t * BLKT;
        irow[t] = i;
        float4 a = (i < nA) ? g_pts[aOff + i]
                            : make_float4(0.f, 0.f, 0.f, 1e30f);
        ax2[t] = -2.0f * a.x; ay2[t] = -2.0f * a.y;
        az2[t] = -2.0f * a.z; aw[t]  = a.w;
    }
    __syncthreads();

    if (diag) {
        #pragma unroll 4
        for (int k = 0; k < TILEB; k++) {
            float4 b = sB[k];
            float s0 = aw[0] + b.w;
            s0 = fmaf(ax2[0], b.x, s0);
            s0 = fmaf(ay2[0], b.y, s0);
            s0 = fmaf(az2[0], b.z, s0);
            float s1 = aw[1] + b.w;
            s1 = fmaf(ax2[1], b.x, s1);
            s1 = fmaf(ay2[1], b.y, s1);
            s1 = fmaf(az2[1], b.z, s1);
            if (__any_sync(0xFFFFFFFFu, fminf(s0, s1) < 40100.0f)) {
                float d0 = fsqrt_approx(fmaxf(s0, 0.0f));
                if (d0 < (float)NTOT && (chunkBase + k) > irow[0])
                    atomicAdd(&myh[(int)d0], 1);
                float d1 = fsqrt_approx(fmaxf(s1, 0.0f));
                if (d1 < (float)NTOT && (chunkBase + k) > irow[1])
                    atomicAdd(&myh[(int)d1], 1);
            }
        }
    } else {
        #pragma unroll 4
        for (int k = 0; k < TILEB; k++) {
            float4 b = sB[k];
            float s0 = aw[0] + b.w;
            s0 = fmaf(ax2[0], b.x, s0);
            s0 = fmaf(ay2[0], b.y, s0);
            s0 = fmaf(az2[0], b.z, s0);
            float s1 = aw[1] + b.w;
            s1 = fmaf(ax2[1], b.x, s1);
            s1 = fmaf(ay2[1], b.y, s1);
            s1 = fmaf(az2[1], b.z, s1);
            if (__any_sync(0xFFFFFFFFu, fminf(s0, s1) < 40100.0f)) {
                float d0 = fsqrt_approx(fmaxf(s0, 0.0f));
                if (d0 < (float)NTOT) atomicAdd(&myh[(int)d0], 1);
                float d1 = fsqrt_approx(fmaxf(s1, 0.0f));
                if (d1 < (float)NTOT) atomicAdd(&myh[(int)d1], 1);
            }
        }
    }
    __syncthreads();

    for (int t = tid; t < NTOT; t += BLKT) {
        int v = sh[t] + sh[NTOT + t] + sh[2 * NTOT + t] + sh[3 * NTOT + t];
        if (v) atomicAdd(&g_hist[histIdx * NTOT + t], v);
    }
}

// Single block: normalize all 800 outputs, then zero g_hist for next replay.
__global__ void finalize_kernel(const float* __restrict__ count_in,
                                float* __restrict__ out,
                                const float* __restrict__ rs,
                                int n0, int n1)
{
    int idx = threadIdx.x;
    if (idx < 4 * NTOT) {
        int k  = idx % NTOT;
        int ij = idx / NTOT;
        int histIdx = (ij == 0) ? 0 : ((ij == 3) ? 2 : 1);
        float mult  = (ij == 0 || ij == 3) ? 2.0f : 1.0f;
        float na = (float)((ij >> 1) ? n1 : n0);
        float nb = (float)((ij & 1) ? n1 : n0);
        float vol = rs[0] * rs[1] * rs[2];

        float counts = (float)g_hist[histIdx * NTOT + k] * mult;
        double r = 0.025 + (double)k * 0.05;
        float sv = (float)(r * 0.05 * 2.0 * 3.14159265358979323846 * 3.0);
        float density = nb / vol;
        float res = counts / density / sv / na;
        out[idx] = count_in[idx] + res;
    }
    __syncthreads();
    if (idx < 3 * NTOT) g_hist[idx] = 0;
}

extern "C" void kernel_launch(void* const* d_in, const int* in_sizes, int n_in,
                              void* d_out, int out_size)
{
    const float* pos0  = (const float*)d_in[0];
    const float* pos1  = (const float*)d_in[1];
    const float* count = (const float*)d_in[2];
    const float* rs    = (const float*)d_in[3];
    int n0 = in_sizes[0] / 3;
    int n1 = in_sizes[1] / 3;
    float* out = (float*)d_out;

    sort_kernel<<<2 * GROUPS, SORTT>>>(pos0, pos1, rs, n0, n1);

    int nb0 = (n0 + TILEA - 1) / TILEA;
    int nb1 = (n1 + TILEA - 1) / TILEA;
    int T0 = nb0 * (nb0 + 1) / 2;
    int C  = nb0 * nb1;
    int T1 = nb1 * (nb1 + 1) / 2;
    pair_fused_kernel<<<4 * (T0 + C + T1), BLKT>>>(n0, n1, nb0, nb1, T0, C);

    finalize_kernel<<<1, 4 * NTOT>>>(count, out, rs, n0, n1);
}

// round 15
// speedup vs baseline: 1.1248x; 1.0830x over previous
#include <cuda_runtime.h>

#define NTOT 200      // histogram bins
#define TILEA 256     // A rows per block
#define TILEB 64      // B cols per block (2 waves of 16 blocks/SM)
#define BLKT 128      // pair-kernel threads (2 A rows per thread)
#define NWARP 4
#define NXB 64        // x buckets per band
#define NYB 4         // y bands
#define NBUCK (NXB * NYB)
#define GROUPS 16     // sorter blocks per array
#define BPB (NBUCK / GROUPS)
#define SORTT 512
#define SBATCH 8
#define MAXPTS 16384

// Sorted (y-band major, x minor) & prescaled points:
// (x,y,z)*real_size*20, w=|p|^2.
__device__ float4 g_pts[MAXPTS];
// 3 raw integer histograms: [0]=00-tri, [1]=01-cross, [2]=11-tri.
// finalize_kernel re-zeroes after reading -> graph replays start clean.
__device__ int g_hist[3 * NTOT];

__device__ __forceinline__ float fsqrt_approx(float x) {
    float r;
    asm("sqrt.approx.f32 %0, %1;" : "=f"(r) : "f"(x));
    return r;
}

__device__ __forceinline__ int bucket_of(float xu, float yu) {
    int xb = max(0, min(NXB - 1, (int)(xu * (float)NXB)));
    int yb = max(0, min(NYB - 1, (int)(yu * (float)NYB)));
    return yb * NXB + xb;
}

// Decentralized counting sort on (y-band, x): 2*GROUPS blocks, no inter-block
// communication. Every block re-derives the FULL bucket count (batched loads,
// MLP=SBATCH), scans locally, scatters only owned buckets. Within-bucket
// order race-dependent -> fine (histogram is permutation-invariant).
__global__ __launch_bounds__(SORTT) void sort_kernel(
    const float* __restrict__ pos0, const float* __restrict__ pos1,
    const float* __restrict__ rs, int n0, int n1)
{
    __shared__ int cnt[NBUCK];
    __shared__ int cur[BPB];

    const int arr = blockIdx.x / GROUPS;
    const int grp = blockIdx.x - arr * GROUPS;
    const float* p = arr ? pos1 : pos0;
    const int n    = arr ? n1 : n0;
    const int base = arr ? n0 : 0;
    const int lo   = grp * BPB;
    const int tid  = threadIdx.x;

    const float r0 = rs[0] * 20.0f, r1 = rs[1] * 20.0f, r2 = rs[2] * 20.0f;

    for (int t = tid; t < NBUCK; t += SORTT) cnt[t] = 0;
    __syncthreads();

    for (int b0 = 0; b0 < n; b0 += SORTT * SBATCH) {
        float xv[SBATCH], yv[SBATCH];
        bool  ok[SBATCH];
        #pragma unroll
        for (int k = 0; k < SBATCH; k++) {
            int i = b0 + tid + k * SORTT;
            ok[k] = (i < n);
            xv[k] = ok[k] ? p[3 * i + 0] : 0.0f;
            yv[k] = ok[k] ? p[3 * i + 1] : 0.0f;
        }
        #pragma unroll
        for (int k = 0; k < SBATCH; k++)
            if (ok[k]) atomicAdd(&cnt[bucket_of(xv[k], yv[k])], 1);
    }
    __syncthreads();

    if (tid < 32) {
        int v[8], s = 0;
        #pragma unroll
        for (int j = 0; j < 8; j++) { v[j] = cnt[tid * 8 + j]; s += v[j]; }
        int e = s;
        #pragma unroll
        for (int d = 1; d < 32; d <<= 1) {
            int t = __shfl_up_sync(0xFFFFFFFFu, e, d);
            if (tid >= d) e += t;
        }
        e -= s;
        #pragma unroll
        for (int j = 0; j < 8; j++) { int t = v[j]; cnt[tid * 8 + j] = e; e += t; }
    }
    __syncthreads();
    if (tid < BPB) cur[tid] = cnt[lo + tid];
    __syncthreads();

    for (int b0 = 0; b0 < n; b0 += SORTT * SBATCH) {
        float xv[SBATCH], yv[SBATCH];
        int   bk[SBATCH];
        #pragma unroll
        for (int k = 0; k < SBATCH; k++) {
            int i = b0 + tid + k * SORTT;
            bool ok = (i < n);
            xv[k] = ok ? p[3 * i + 0] : 0.0f;
            yv[k] = ok ? p[3 * i + 1] : 0.0f;
            bk[k] = ok ? 0 : -1;
        }
        #pragma unroll
        for (int k = 0; k < SBATCH; k++)
            if (bk[k] == 0) bk[k] = bucket_of(xv[k], yv[k]);
        #pragma unroll
        for (int k = 0; k < SBATCH; k++) {
            int b = bk[k];
            if (b >= lo && b < lo + BPB) {
                int i = b0 + tid + k * SORTT;
                float z = p[3 * i + 2];
                int pos = atomicAdd(&cur[b - lo], 1);
                float sx = xv[k] * r0, sy = yv[k] * r1, sz = z * r2;
                float q = sx * sx; q = fmaf(sy, sy, q); q = fmaf(sz, sz, q);
                g_pts[base + pos] = make_float4(sx, sy, sz, q);
            }
        }
    }
}

// Invert upper-triangle linear index t -> (bi, bj), bj >= bi.
__device__ __forceinline__ void tri_decode(int t, int n, int& bi, int& bj) {
    float fn = (float)(2 * n + 1);
    int b = (int)((fn - sqrtf(fmaxf(fn * fn - 8.0f * (float)t, 0.0f))) * 0.5f);
    if (b < 0) b = 0;
    if (b > n - 1) b = n - 1;
    while (b > 0 && t < b * (2 * n - b + 1) / 2) b--;
    while (b < n - 1 && t >= (b + 1) * (2 * n - b) / 2) b++;
    bi = b;
    bj = b + (t - b * (2 * n - b + 1) / 2);
}

// Derive a conservative (x,y) bounding range for a sorted run [s..e] from its
// endpoint values. Bands padded by +/-0.5 scaled units against fp boundary
// flips; x padded by one bucket width (+1). Band-spanning runs: x-full.
__device__ __forceinline__ void run_range(
    float4 ps, float4 pe, float yw, float xpad,
    float& xlo, float& xhi, float& ylo, float& yhi)
{
    int bs = (int)((ps.y - 0.5f) / yw);   // trunc-to-0 ok: only loosens bound
    int be = (int)((pe.y + 0.5f) / yw);
    if (bs == be) { xlo = ps.x - xpad; xhi = pe.x + xpad; }
    else          { xlo = -1e9f;       xhi = 1e9f; }
    ylo = (float)bs * yw - 1.0f;
    yhi = (float)(be + 1) * yw + 1.0f;
}

// All three pair regions in one grid; 256x64 blocks (2 waves/SM); 2D
// (x,y-band) analytic cull replaces the x-only cull. Inner loop identical to
// the proven R10 kernel.
__global__ __launch_bounds__(BLKT, 16) void pair_fused_kernel(
    const float* __restrict__ rs,
    int n0, int n1, int nb0, int nb1, int T0, int C)
{
    __shared__ float4 sB[TILEB];
    __shared__ int    sh[NWARP * NTOT];

    int w    = blockIdx.x >> 2;
    int quar = blockIdx.x & 3;
    int bi, bj, aOff, bOff, nA, nB, histIdx;
    bool diag;
    if (w < T0) {                     // 0-0 triangle
        tri_decode(w, nb0, bi, bj);
        aOff = 0; bOff = 0; nA = n0; nB = n0; histIdx = 0;
        diag = (bi == bj);
    } else if (w < T0 + C) {          // 0-1 cross
        int u = w - T0;
        bi = u / nb1; bj = u - bi * nb1;
        aOff = 0; nA = n0; bOff = n0; nB = n1; histIdx = 1;
        diag = false;
    } else {                          // 1-1 triangle
        int u = w - T0 - C;
        tri_decode(u, nb1, bi, bj);
        aOff = n0; bOff = n0; nA = n1; nB = n1; histIdx = 2;
        diag = (bi == bj);
    }
    const int rowStart  = bi * TILEA;
    const int chunkBase = bj * TILEA + quar * TILEB;
    if (chunkBase >= nB) return;

    // ---- 2D bbox cull (exact lower bound on pair distance) ----
    {
        const float yw   = rs[1] * 20.0f * (1.0f / NYB);   // band width
        const float xpad = rs[0] * 20.0f * (1.0f / NXB) + 1.0f;
        float4 as = g_pts[aOff + rowStart];
        float4 ae = g_pts[aOff + min(rowStart + TILEA - 1, nA - 1)];
        float4 bs = g_pts[bOff + chunkBase];
        float4 be = g_pts[bOff + min(chunkBase + TILEB - 1, nB - 1)];
        float axl, axh, ayl, ayh, bxl, bxh, byl, byh;
        run_range(as, ae, yw, xpad, axl, axh, ayl, ayh);
        run_range(bs, be, yw, xpad, bxl, bxh, byl, byh);
        float gx = fmaxf(0.0f, fmaxf(bxl - axh, axl - bxh));
        float gy = fmaxf(0.0f, fmaxf(byl - ayh, ayl - byh));
        // culled pairs have d^2 > 200.2^2 -> bin >= 200 -> dropped by ref too
        if (fmaf(gx, gx, gy * gy) > 40100.0f) return;
    }

    const int tid = threadIdx.x;
    const int wid = tid >> 5;
    int* myh = &sh[wid * NTOT];

    #pragma unroll
    for (int idx = tid; idx < NWARP * NTOT; idx += BLKT) sh[idx] = 0;

    if (tid < TILEB) {
        int j = chunkBase + tid;
        sB[tid] = (j < nB) ? g_pts[bOff + j]
                           : make_float4(0.f, 0.f, 0.f, 1e30f);
    }

    float ax2[2], ay2[2], az2[2], aw[2];
    int   irow[2];
    #pragma unroll
    for (int t = 0; t < 2; t++) {
        int i = rowStart + tid + t * BLKT;
        irow[t] = i;
        float4 a = (i < nA) ? g_pts[aOff + i]
                            : make_float4(0.f, 0.f, 0.f, 1e30f);
        ax2[t] = -2.0f * a.x; ay2[t] = -2.0f * a.y;
        az2[t] = -2.0f * a.z; aw[t]  = a.w;
    }
    __syncthreads();

    if (diag) {
        #pragma unroll 4
        for (int k = 0; k < TILEB; k++) {
            float4 b = sB[k];
            #pragma unroll
            for (int t = 0; t < 2; t++) {
                float s = aw[t] + b.w;
                s = fmaf(ax2[t], b.x, s);
                s = fmaf(ay2[t], b.y, s);
                s = fmaf(az2[t], b.z, s);
                float d = fsqrt_approx(fmaxf(s, 0.0f));
                if (d < (float)NTOT && (chunkBase + k) > irow[t])
                    atomicAdd(&myh[(int)d], 1);
            }
        }
    } else {
        #pragma unroll 4
        for (int k = 0; k < TILEB; k++) {
            float4 b = sB[k];
            #pragma unroll
            for (int t = 0; t < 2; t++) {
                float s = aw[t] + b.w;
                s = fmaf(ax2[t], b.x, s);
                s = fmaf(ay2[t], b.y, s);
                s = fmaf(az2[t], b.z, s);
                float d = fsqrt_approx(fmaxf(s, 0.0f));
                if (d < (float)NTOT)
                    atomicAdd(&myh[(int)d], 1);
            }
        }
    }
    __syncthreads();

    for (int t = tid; t < NTOT; t += BLKT) {
        int v = sh[t] + sh[NTOT + t] + sh[2 * NTOT + t] + sh[3 * NTOT + t];
        if (v) atomicAdd(&g_hist[histIdx * NTOT + t], v);
    }
}

// Single block: normalize all 800 outputs (fp32 only — the double-precision
// slice-volume math cost ~4us of FP64 on one SM), then zero g_hist.
__global__ void finalize_kernel(const float* __restrict__ count_in,
                                float* __restrict__ out,
                                const float* __restrict__ rs,
                                int n0, int n1)
{
    int idx = threadIdx.x;
    if (idx < 4 * NTOT) {
        int k  = idx % NTOT;
        int ij = idx / NTOT;
        int histIdx = (ij == 0) ? 0 : ((ij == 3) ? 2 : 1);
        float mult  = (ij == 0 || ij == 3) ? 2.0f : 1.0f;
        float na = (float)((ij >> 1) ? n1 : n0);
        float nb = (float)((ij & 1) ? n1 : n0);
        float vol = rs[0] * rs[1] * rs[2];

        float counts = (float)g_hist[histIdx * NTOT + k] * mult;
        float r  = fmaf((float)k, 0.05f, 0.025f);
        float sv = r * 0.94247779607694f;   // 0.05 * 2 * pi * 3
        float density = nb / vol;
        float res = counts / density / sv / na;
        out[idx] = count_in[idx] + res;
    }
    __syncthreads();
    if (idx < 3 * NTOT) g_hist[idx] = 0;
}

extern "C" void kernel_launch(void* const* d_in, const int* in_sizes, int n_in,
                              void* d_out, int out_size)
{
    const float* pos0  = (const float*)d_in[0];
    const float* pos1  = (const float*)d_in[1];
    const float* count = (const float*)d_in[2];
    const float* rs    = (const float*)d_in[3];
    int n0 = in_sizes[0] / 3;
    int n1 = in_sizes[1] / 3;
    float* out = (float*)d_out;

    sort_kernel<<<2 * GROUPS, SORTT>>>(pos0, pos1, rs, n0, n1);

    int nb0 = (n0 + TILEA - 1) / TILEA;
    int nb1 = (n1 + TILEA - 1) / TILEA;
    int T0 = nb0 * (nb0 + 1) / 2;
    int C  = nb0 * nb1;
    int T1 = nb1 * (nb1 + 1) / 2;
    pair_fused_kernel<<<4 * (T0 + C + T1), BLKT>>>(rs, n0, n1, nb0, nb1, T0, C);

    finalize_kernel<<<1, 4 * NTOT>>>(count, out, rs, n0, n1);
}